// round 6
// baseline (speedup 1.0000x reference)
#include <cuda_runtime.h>

#define B 256
#define C 50000
#define D 512
#define ALPHA 0.5f

// ---- scan blocks ----
#define OH_SLICES 8
#define NB_OH (B * OH_SLICES)       // 2048 scan blocks (entire wave 1)
#define OH_ROW4 (C / 4)             // 12500 float4 per row
#define OH_PER_SLICE ((OH_ROW4 + OH_SLICES - 1) / OH_SLICES)  // 1563

// ---- result blocks ----
#define NB_RES B                    // 256

// ---- copy blocks: 256 thr x 8 float4 = 16 rows of D=512 ----
#define COPY_PER_THREAD 8
#define ROWS_PER_BLOCK 16
#define NB_COPY ((C * D / 4) / (256 * COPY_PER_THREAD))  // 3125, exact
#define NB_TOTAL (NB_OH + NB_RES + NB_COPY)
#define NB_CONSUMERS (NB_RES + NB_COPY)

__device__ int g_labels[B];
__device__ unsigned int g_scan = 0;   // scan-block completion counter
__device__ unsigned int g_fin  = 0;   // consumer completion counter (reset)

__device__ __forceinline__ void wait_scan_done() {
    if (threadIdx.x == 0) {
        while (atomicAdd(&g_scan, 0u) < NB_OH) __nanosleep(64);
    }
    __syncthreads();
    __threadfence();
}

__device__ __forceinline__ void consumer_retire() {
    __syncthreads();
    if (threadIdx.x == 0) {
        __threadfence();
        unsigned int f = atomicAdd(&g_fin, 1u);
        if (f == NB_CONSUMERS - 1) {   // very last consumer resets for replay
            g_scan = 0;
            g_fin = 0;
            __threadfence();
        }
    }
}

__global__ void __launch_bounds__(256) center_loss_kernel(
    const float* __restrict__ x,
    const float* __restrict__ onehot,
    const float* __restrict__ centers,
    float* __restrict__ result,
    float* __restrict__ new_centers) {
    int blk = blockIdx.x;
    int tid = threadIdx.x;

    if (blk < NB_OH) {
        // ================= scan: find nonzero column of onehot row =========
        int b = blk >> 3;
        int slice = blk & 7;
        const float4* row = reinterpret_cast<const float4*>(onehot) +
                            (size_t)b * OH_ROW4;
        int lo = slice * OH_PER_SLICE;
        int hi = lo + OH_PER_SLICE;
        if (hi > OH_ROW4) hi = OH_ROW4;
        int found = -1;
        for (int i = lo + tid; i < hi; i += 256) {
            float4 v = row[i];
            if (v.x != 0.0f) found = 4 * i + 0;
            if (v.y != 0.0f) found = 4 * i + 1;
            if (v.z != 0.0f) found = 4 * i + 2;
            if (v.w != 0.0f) found = 4 * i + 3;
        }
        if (found >= 0) g_labels[b] = found;
        __syncthreads();
        __threadfence();
        if (tid == 0) atomicAdd(&g_scan, 1u);
    } else if (blk < NB_OH + NB_RES) {
        // ================= result: ||x[b] - centers[l]||^2 =================
        int b = blk - NB_OH;
        __shared__ float s_x[D];
        __shared__ float s_warp[8];

        // prefetch x row (independent of scan)
        const float* xb = x + (size_t)b * D;
        #pragma unroll
        for (int k = 0; k < D / 256; k++)
            s_x[tid + k * 256] = xb[tid + k * 256];

        wait_scan_done();

        int l = g_labels[b];
        const float* cl = centers + (size_t)l * D;
        float acc = 0.0f;
        #pragma unroll
        for (int k = 0; k < D / 256; k++) {
            int d = tid + k * 256;
            float df = s_x[d] - cl[d];
            acc += df * df;
        }
        #pragma unroll
        for (int off = 16; off > 0; off >>= 1)
            acc += __shfl_down_sync(0xFFFFFFFFu, acc, off);
        if ((tid & 31) == 0) s_warp[tid >> 5] = acc;
        __syncthreads();
        if (tid == 0) {
            float tot = 0.0f;
            #pragma unroll
            for (int w = 0; w < 8; w++) tot += s_warp[w];
            result[b] = tot;
        }
        consumer_retire();
    } else {
        // ================= copy (+ rare fixup of owned rows) ===============
        int cb = blk - NB_OH - NB_RES;

        // ---- fast path FIRST: keep front-batched MLP intact ----
        const float4* src = reinterpret_cast<const float4*>(centers);
        float4* dst = reinterpret_cast<float4*>(new_centers);
        size_t base = (size_t)cb * (256 * COPY_PER_THREAD) + tid;
        #pragma unroll
        for (int k = 0; k < COPY_PER_THREAD; k++) {
            size_t idx = base + (size_t)k * 256;
            dst[idx] = src[idx];
        }

        // ---- ordering: scan done (spin ~0: scan occupied wave 1) ----
        wait_scan_done();

        // ---- check owned rows [r0, r0+16) against labels ----
        __shared__ int s_lab[B];
        __shared__ unsigned int s_mask;
        s_lab[tid] = g_labels[tid];
        if (tid == 0) s_mask = 0u;
        __syncthreads();

        int r0 = cb * ROWS_PER_BLOCK;
        int l = s_lab[tid];
        if (l >= r0 && l < r0 + ROWS_PER_BLOCK)
            atomicOr(&s_mask, 1u << (l - r0));
        __syncthreads();

        if (s_mask != 0u) {
            unsigned int mask = s_mask;
            while (mask) {
                int ri = __ffs(mask) - 1;
                mask &= mask - 1;
                int row = r0 + ri;
                int n = 0;
                float sx0 = 0.0f, sx1 = 0.0f;
                for (int m = 0; m < B; m++) {
                    if (s_lab[m] == row) {
                        n++;
                        const float* xm = x + (size_t)m * D;
                        sx0 += xm[tid];
                        sx1 += xm[tid + 256];
                    }
                }
                float inv = 1.0f / ((float)n + 1.0f);
                float fn = (float)n;
                size_t rb = (size_t)row * D;
                float c0 = centers[rb + tid];
                float c1 = centers[rb + tid + 256];
                new_centers[rb + tid]       = c0 - ALPHA * (fn * c0 - sx0) * inv;
                new_centers[rb + tid + 256] = c1 - ALPHA * (fn * c1 - sx1) * inv;
            }
        }
        consumer_retire();
    }
}

extern "C" void kernel_launch(void* const* d_in, const int* in_sizes, int n_in,
                              void* d_out, int out_size) {
    const float* x       = (const float*)d_in[0];
    const float* onehot  = (const float*)d_in[1];
    const float* centers = (const float*)d_in[2];

    float* result      = (float*)d_out;        // [B, 1]
    float* new_centers = (float*)d_out + B;    // [C, D]

    center_loss_kernel<<<NB_TOTAL, 256>>>(x, onehot, centers,
                                          result, new_centers);
}

// round 7
// speedup vs baseline: 1.1862x; 1.1862x over previous
#include <cuda_runtime.h>

#define B 256
#define C 50000
#define D 512
#define ALPHA 0.5f

// ---- scan blocks ----
#define OH_SLICES 8
#define NB_OH (B * OH_SLICES)       // 2048 scan blocks, first in grid
#define OH_ROW4 (C / 4)             // 12500 float4 per row
#define OH_PER_SLICE 1563           // ceil(12500/8); 8*1563 covers row
#define SCAN_ITERS 7                // ceil(1563/256)

// ---- copy blocks: 256 thr x 8 float4 = 16 rows of D=512 ----
#define COPY_PER_THREAD 8
#define NB_COPY ((C * D / 4) / (256 * COPY_PER_THREAD))  // 3125, exact
#define NB_TOTAL (NB_OH + NB_COPY)

__device__ int g_labels[B];

// Fused kernel: onehot scan (dot-with-iota, finder computes result[b] inline)
// + centers->new_centers bulk copy. Proven-roofline structure from R2/R3.
__global__ void __launch_bounds__(256) fused_kernel(
    const float* __restrict__ x,
    const float* __restrict__ onehot,
    const float* __restrict__ centers,
    float* __restrict__ result,
    float4* __restrict__ new_centers4) {
    int blk = blockIdx.x;
    int tid = threadIdx.x;

    if (blk < NB_OH) {
        // ================ scan: sum v[i]*(i+1) over slice =================
        int b = blk >> 3;
        int slice = blk & 7;
        const float4* row = reinterpret_cast<const float4*>(onehot) +
                            (size_t)b * OH_ROW4;
        int lo = slice * OH_PER_SLICE;
        int hi = lo + OH_PER_SLICE;
        if (hi > OH_ROW4) hi = OH_ROW4;

        float acc = 0.0f;
        #pragma unroll
        for (int k = 0; k < SCAN_ITERS; k++) {
            int i = lo + tid + k * 256;
            float4 v = (i < hi) ? row[i] : make_float4(0.f, 0.f, 0.f, 0.f);
            float fi = (float)(4 * i);
            acc += v.x * (fi + 1.0f);
            acc += v.y * (fi + 2.0f);
            acc += v.z * (fi + 3.0f);
            acc += v.w * (fi + 4.0f);
        }

        // block reduction (exact: at most one nonzero term in whole row)
        __shared__ float s_warp[8];
        __shared__ float s_sum;
        #pragma unroll
        for (int off = 16; off > 0; off >>= 1)
            acc += __shfl_down_sync(0xFFFFFFFFu, acc, off);
        if ((tid & 31) == 0) s_warp[tid >> 5] = acc;
        __syncthreads();
        if (tid == 0) {
            float t = 0.0f;
            #pragma unroll
            for (int w = 0; w < 8; w++) t += s_warp[w];
            s_sum = t;
        }
        __syncthreads();

        float s = s_sum;
        if (s > 0.5f) {
            // this block found the label: s == label+1 exactly
            int l = (int)(s + 0.5f) - 1;
            if (tid == 0) g_labels[b] = l;

            // compute result[b] = ||x[b] - centers[l]||^2 inline
            const float* xb = x + (size_t)b * D;
            const float* cl = centers + (size_t)l * D;
            float r = 0.0f;
            #pragma unroll
            for (int k = 0; k < D / 256; k++) {
                int d = tid + k * 256;
                float df = xb[d] - cl[d];
                r += df * df;
            }
            #pragma unroll
            for (int off = 16; off > 0; off >>= 1)
                r += __shfl_down_sync(0xFFFFFFFFu, r, off);
            if ((tid & 31) == 0) s_warp[tid >> 5] = r;
            __syncthreads();
            if (tid == 0) {
                float t = 0.0f;
                #pragma unroll
                for (int w = 0; w < 8; w++) t += s_warp[w];
                result[b] = t;
            }
        }
    } else {
        // ================ bulk copy: 8 float4/thread, exact ================
        int cb = blk - NB_OH;
        const float4* src = reinterpret_cast<const float4*>(centers);
        size_t base = (size_t)cb * (256 * COPY_PER_THREAD) + tid;
        #pragma unroll
        for (int k = 0; k < COPY_PER_THREAD; k++) {
            size_t idx = base + (size_t)k * 256;
            new_centers4[idx] = src[idx];
        }
    }
}

// Fixup: first-occurrence block per class rewrites that class's row.
// (result[b] already written by the fused kernel's finder blocks.)
__global__ void __launch_bounds__(256) fixup_kernel(
    const float* __restrict__ x,
    const float* __restrict__ centers,
    float* __restrict__ new_centers) {
    int b = blockIdx.x;
    int tid = threadIdx.x;

    __shared__ int s_lab[B];
    __shared__ int s_match[B];
    __shared__ int s_cnt;
    __shared__ int s_first;

    s_lab[tid] = g_labels[tid];
    if (tid == 0) { s_cnt = 0; s_first = B; }
    __syncthreads();

    int l = s_lab[b];
    if (s_lab[tid] == l) {
        int pos = atomicAdd(&s_cnt, 1);
        s_match[pos] = tid;
        atomicMin(&s_first, tid);
    }
    __syncthreads();

    if (b != s_first) return;   // only lowest-indexed holder writes

    int n = s_cnt;
    float inv = 1.0f / ((float)n + 1.0f);
    float fn = (float)n;
    #pragma unroll
    for (int k = 0; k < D / 256; k++) {
        int d = tid + k * 256;
        float sx = 0.0f;
        for (int m = 0; m < n; m++)
            sx += x[(size_t)s_match[m] * D + d];
        float c = centers[(size_t)l * D + d];
        new_centers[(size_t)l * D + d] = c - ALPHA * (fn * c - sx) * inv;
    }
}

extern "C" void kernel_launch(void* const* d_in, const int* in_sizes, int n_in,
                              void* d_out, int out_size) {
    const float* x       = (const float*)d_in[0];
    const float* onehot  = (const float*)d_in[1];
    const float* centers = (const float*)d_in[2];

    float* result      = (float*)d_out;        // [B, 1]
    float* new_centers = (float*)d_out + B;    // [C, D]

    fused_kernel<<<NB_TOTAL, 256>>>(x, onehot, centers, result,
                                    reinterpret_cast<float4*>(new_centers));
    fixup_kernel<<<B, 256>>>(x, centers, new_centers);
}